// round 16
// baseline (speedup 1.0000x reference)
#include <cuda_runtime.h>
#include <cuda_bf16.h>
#include <math.h>
#include <stdint.h>

#define Bb 16
#define Tt 1600
#define Ee 512
#define Oo 2048
#define Uu 200
#define Ss 401
#define NCH 32
#define TCH (Tt / NCH)
#define CH 24

#define NEGF  (-1.0e30f)
#define THRF  (-1.0e29f)
#define NEG_D (-1.0e30)
#define THR_D (-1.0e29)
#define SENT_D (-2000.4586751453871)

#define NA (Bb * Tt * Ee)
#define NW (Oo * Ee)
#define NB_CVT ((NA + NW) / 1024)

// ------------------------- static scratch -------------------------
static __device__ float          d_logits[(size_t)Bb * Tt * Oo];
static __device__ __nv_bfloat16  d_hsb[(size_t)NA];
static __device__ __nv_bfloat16  d_Wb[(size_t)NW];
static __device__ float  d_lpBlank[Bb * Tt];
static __device__ float  d_lpLabel[(size_t)Bb * Tt * Uu];
static __device__ float  d_alphaU[(size_t)Bb * Tt * Uu];
static __device__ double d_betaU[(size_t)Bb * Tt * Uu];
static __device__ double d_partM[(size_t)Bb * Uu * NCH];
static __device__ double d_partS[(size_t)Bb * Uu * NCH];
static __device__ double d_lossB[Bb];
static __device__ int    d_ys[Bb * Uu];
static __device__ int    d_hl[Bb];
static __device__ int    d_mode64;

// ============================================================================
// K0: fused repack + bf16 convert
// ============================================================================
__global__ __launch_bounds__(256) void k_prep(const float* __restrict__ hs,
                                              const float* __restrict__ Wm,
                                              const void* ysRaw, const void* hlRaw)
{
    const int tid = threadIdx.x;
    if (blockIdx.x == NB_CVT) {
        const int* y32 = (const int*)ysRaw;
        int anyPos = __syncthreads_or(y32[2 * tid + 1] > 0);
        const int m64 = (anyPos == 0);
        if (tid == 0) d_mode64 = m64;
        for (int i = tid; i < Bb * Uu; i += 256)
            d_ys[i] = m64 ? (int)((const long long*)ysRaw)[i] : ((const int*)ysRaw)[i];
        if (tid < Bb)
            d_hl[tid] = m64 ? (int)((const long long*)hlRaw)[tid] : ((const int*)hlRaw)[tid];
        return;
    }
    const size_t i = ((size_t)blockIdx.x * 256 + tid) * 4;
    if (i < (size_t)NA) {
        float4 v = *(const float4*)(hs + i);
        ushort4 o;
        o.x = __bfloat16_as_ushort(__float2bfloat16_rn(v.x));
        o.y = __bfloat16_as_ushort(__float2bfloat16_rn(v.y));
        o.z = __bfloat16_as_ushort(__float2bfloat16_rn(v.z));
        o.w = __bfloat16_as_ushort(__float2bfloat16_rn(v.w));
        *(ushort4*)(d_hsb + i) = o;
    } else {
        const size_t j = i - NA;
        float4 v = *(const float4*)(Wm + j);
        ushort4 o;
        o.x = __bfloat16_as_ushort(__float2bfloat16_rn(v.x));
        o.y = __bfloat16_as_ushort(__float2bfloat16_rn(v.y));
        o.z = __bfloat16_as_ushort(__float2bfloat16_rn(v.z));
        o.w = __bfloat16_as_ushort(__float2bfloat16_rn(v.w));
        *(ushort4*)(d_Wb + j) = o;
    }
}

// ============================================================================
// cp.async helpers
// ============================================================================
__device__ __forceinline__ void cp16(void* smem, const void* gmem)
{
    uint32_t s = (uint32_t)__cvta_generic_to_shared(smem);
    asm volatile("cp.async.cg.shared.global [%0], [%1], 16;\n" :: "r"(s), "l"(gmem));
}
__device__ __forceinline__ void cp4(void* smem, const void* gmem)
{
    uint32_t s = (uint32_t)__cvta_generic_to_shared(smem);
    asm volatile("cp.async.ca.shared.global [%0], [%1], 4;\n" :: "r"(s), "l"(gmem));
}
#define CP_COMMIT() asm volatile("cp.async.commit_group;\n" ::: "memory")
#define CP_WAIT(n)  asm volatile("cp.async.wait_group %0;\n" :: "n"(n) : "memory")

// ============================================================================
// K1: bf16 mma GEMM (measured 222 us) — unchanged
// ============================================================================
__global__ __launch_bounds__(512) void k_gemm(const float* __restrict__ bias)
{
    __shared__ __align__(16) __nv_bfloat16 As[2][128][40];
    __shared__ __align__(16) __nv_bfloat16 Ws[2][128][40];

    const int tid  = threadIdx.x;
    const int bn   = blockIdx.x, bm = blockIdx.y;
    const int lane = tid & 31;
    const int warp = tid >> 5;
    const int g    = lane >> 2;
    const int t    = lane & 3;
    const int wm   = warp >> 2;
    const int wn   = warp & 3;

    const int r = tid >> 2;
    const int q = (tid & 3) << 3;
    const __nv_bfloat16* Ap = d_hsb + ((size_t)(bm * 128 + r)) * Ee + q;
    const __nv_bfloat16* Wp = d_Wb  + ((size_t)(bn * 128 + r)) * Ee + q;

    float acc[2][4][4];
#pragma unroll
    for (int mi = 0; mi < 2; mi++)
#pragma unroll
        for (int ni = 0; ni < 4; ni++)
#pragma unroll
            for (int c = 0; c < 4; c++) acc[mi][ni][c] = 0.f;

    cp16(&As[0][r][q], Ap);
    cp16(&Ws[0][r][q], Wp);
    CP_COMMIT();

    const int rA0 = wm * 32 + g;
    const int nB0 = wn * 32 + g;

#pragma unroll 1
    for (int kt = 0; kt < 16; kt++) {
        const int buf = kt & 1;
        if (kt < 15) {
            cp16(&As[buf ^ 1][r][q], Ap + (kt + 1) * 32);
            cp16(&Ws[buf ^ 1][r][q], Wp + (kt + 1) * 32);
            CP_COMMIT();
            CP_WAIT(1);
        } else {
            CP_WAIT(0);
        }
        __syncthreads();
#pragma unroll
        for (int ks = 0; ks < 2; ks++) {
            const int kk = ks * 16;
            uint32_t af[2][4], bf[4][2];
#pragma unroll
            for (int mi = 0; mi < 2; mi++) {
                const int rr = rA0 + mi * 16;
                af[mi][0] = *(const uint32_t*)&As[buf][rr][kk + 2 * t];
                af[mi][1] = *(const uint32_t*)&As[buf][rr + 8][kk + 2 * t];
                af[mi][2] = *(const uint32_t*)&As[buf][rr][kk + 2 * t + 8];
                af[mi][3] = *(const uint32_t*)&As[buf][rr + 8][kk + 2 * t + 8];
            }
#pragma unroll
            for (int ni = 0; ni < 4; ni++) {
                const int nn = nB0 + ni * 8;
                bf[ni][0] = *(const uint32_t*)&Ws[buf][nn][kk + 2 * t];
                bf[ni][1] = *(const uint32_t*)&Ws[buf][nn][kk + 2 * t + 8];
            }
#pragma unroll
            for (int mi = 0; mi < 2; mi++)
#pragma unroll
                for (int ni = 0; ni < 4; ni++) {
                    asm volatile(
                        "mma.sync.aligned.m16n8k16.row.col.f32.bf16.bf16.f32 "
                        "{%0,%1,%2,%3}, {%4,%5,%6,%7}, {%8,%9}, {%0,%1,%2,%3};"
                        : "+f"(acc[mi][ni][0]), "+f"(acc[mi][ni][1]),
                          "+f"(acc[mi][ni][2]), "+f"(acc[mi][ni][3])
                        : "r"(af[mi][0]), "r"(af[mi][1]),
                          "r"(af[mi][2]), "r"(af[mi][3]),
                          "r"(bf[ni][0]), "r"(bf[ni][1]));
                }
        }
        __syncthreads();
    }

#pragma unroll
    for (int mi = 0; mi < 2; mi++) {
        const int row0 = bm * 128 + wm * 32 + mi * 16 + g;
#pragma unroll
        for (int ni = 0; ni < 4; ni++) {
            const int col = bn * 128 + wn * 32 + ni * 8 + 2 * t;
            const float2 bb = *(const float2*)&bias[col];
            float2 v0 = make_float2(acc[mi][ni][0] + bb.x, acc[mi][ni][1] + bb.y);
            float2 v1 = make_float2(acc[mi][ni][2] + bb.x, acc[mi][ni][3] + bb.y);
            *(float2*)(d_logits + (size_t)row0 * Oo + col) = v0;
            *(float2*)(d_logits + (size_t)(row0 + 8) * Oo + col) = v1;
        }
    }
}

// ============================================================================
// K2: row LSE + gather — unchanged (measured 50 us)
// ============================================================================
__global__ __launch_bounds__(256) void k_rowlse()
{
    const int row = blockIdx.x;
    const int b = row / Tt;
    const int tid = threadIdx.x;
    __shared__ float sr[Oo];
    __shared__ float red[32];
    const float4* r4 = (const float4*)(d_logits + (size_t)row * Oo);

    float4 va = r4[tid];
    float4 vb = r4[tid + 256];
    ((float4*)sr)[tid] = va;
    ((float4*)sr)[tid + 256] = vb;
    float m = fmaxf(fmaxf(fmaxf(va.x, va.y), fmaxf(va.z, va.w)),
                    fmaxf(fmaxf(vb.x, vb.y), fmaxf(vb.z, vb.w)));
    for (int o = 16; o; o >>= 1) m = fmaxf(m, __shfl_xor_sync(0xffffffffu, m, o));
    if ((tid & 31) == 0) red[tid >> 5] = m;
    __syncthreads();
    if (tid < 32) {
        float x = (tid < 8) ? red[tid] : -3.0e38f;
        for (int o = 4; o; o >>= 1) x = fmaxf(x, __shfl_xor_sync(0xffffffffu, x, o));
        if (tid == 0) red[0] = x;
    }
    __syncthreads();
    m = red[0];

    float s = __expf(va.x - m) + __expf(va.y - m) + __expf(va.z - m) + __expf(va.w - m)
            + __expf(vb.x - m) + __expf(vb.y - m) + __expf(vb.z - m) + __expf(vb.w - m);
    for (int o = 16; o; o >>= 1) s += __shfl_xor_sync(0xffffffffu, s, o);
    __syncthreads();
    if ((tid & 31) == 0) red[tid >> 5] = s;
    __syncthreads();
    if (tid < 32) {
        float x = (tid < 8) ? red[tid] : 0.f;
        for (int o = 4; o; o >>= 1) x += __shfl_xor_sync(0xffffffffu, x, o);
        if (tid == 0) red[1] = x;
    }
    __syncthreads();
    const float lse = m + logf(red[1]);

    if (tid == 0) d_lpBlank[row] = sr[0] - lse;
    if (tid < Uu) {
        int y = d_ys[b * Uu + tid];
        int c = y < 0 ? 0 : y;
        d_lpLabel[(size_t)row * Uu + tid] = sr[c] - lse;
    }
}

// ============================================================================
// beta LSEs — bit-identical semantics (lse2 == lse3 with g2=NEG_D).
// ============================================================================
__device__ __forceinline__ double lse3_64(double g0, double g1, double g2)
{
    float f0 = (float)g0, f1 = (float)g1, f2 = (float)g2;
    float fm = fmaxf(f0, fmaxf(f1, f2));
    if (fm <= THRF) return NEG_D;
    bool a0 = (f0 == fm);
    bool a1 = !a0 && (f1 == fm);
    double m = a0 ? g0 : (a1 ? g1 : g2);
    float d0 = (float)(g0 - m);
    float d1 = (float)(g1 - m);
    float d2 = (float)(g2 - m);
    double x = ((double)__expf(d0) + (double)__expf(d1))
             + ((double)__expf(d2) - 1.0);
    double y = (x > 0.0) ? (double)log1pf((float)x) : 0.0;
    return m + y;
}
__device__ __forceinline__ double lse2_64(double g0, double g1)
{
    float f0 = (float)g0, f1 = (float)g1;
    float fm = fmaxf(f0, f1);
    if (fm <= THRF) return NEG_D;
    bool a0 = (f0 == fm);
    double m = a0 ? g0 : g1;
    float d0 = (float)(g0 - m);
    float d1 = (float)(g1 - m);
    double x = ((double)__expf(d0) + (double)__expf(d1))
             + (0.0 - 1.0);
    double y = (x > 0.0) ? (double)log1pf((float)x) : 0.0;
    return m + y;
}

// ============================================================================
// K3: alpha (blocks 0..15) / beta (blocks 16..31) — unchanged from R15.
// IDEMPOTENT: launched twice this round to measure its true cost.
// ============================================================================
__global__ __launch_bounds__(224) void k_ab()
{
    const int b = blockIdx.x & (Bb - 1);
    const bool isBeta = (blockIdx.x >= Bb);
    const int i = threadIdx.x;
    __shared__ double bufD[2][408];
    __shared__ bool allowOdd[208];
    __shared__ int s_olen;
    __shared__ __align__(16) float emL[2][CH][Uu];
    __shared__ float emB[2][CH];
    float (*bufF)[408] = (float(*)[408])bufD;

    for (int k = i; k < 408; k += 224) { bufD[0][k] = NEG_D; bufD[1][k] = NEG_D; }
    if (i < 208) allowOdd[i] = false;
    __syncthreads();
    if (!isBeta)
        for (int k = i; k < 408; k += 224) { bufF[0][k] = NEGF; bufF[1][k] = NEGF; }
    if (i >= 1 && i < Uu) {
        int yu = d_ys[b * Uu + i];
        int yp = d_ys[b * Uu + i - 1];
        int cu = yu < 0 ? 0 : yu;
        int cp = yp < 0 ? 0 : yp;
        allowOdd[i] = (cu != cp);
    }
    if (i == 0) {
        int c = 0;
        for (int q = 0; q < Uu; q++) c += (d_ys[b * Uu + q] >= 0);
        s_olen = c;
    }
    __syncthreads();
    const int hlen = d_hl[b];
    const int olen = s_olen;
    const bool act0 = (2 * i <= 400);
    const bool act1 = (2 * i + 1 <= 400);
    const int u = i;
    const size_t blkBase = (size_t)b * Tt;
    const float* lpL = d_lpLabel + blkBase * Uu;
    const float* lpB = d_lpBlank + blkBase;

    auto loadChunk = [&](int nb, int r0) {
        for (int k = i; k < CH * (Uu / 4); k += 224) {
            int tt = k / (Uu / 4);
            int j  = k % (Uu / 4);
            int row = r0 + tt;
            if (row > Tt - 1) row = Tt - 1;
            if (row < 0) row = 0;
            cp16(&emL[nb][tt][j * 4], lpL + (size_t)row * Uu + j * 4);
        }
        if (i < CH) {
            int row = r0 + i;
            if (row > Tt - 1) row = Tt - 1;
            if (row < 0) row = 0;
            cp4(&emB[nb][i], lpB + row);
        }
    };

    if (!isBeta) {
        float acur0 = NEGF, acur1 = NEGF;
        if (act0) {
            acur0 = (2 * i <= 1) ? lpB[0] : NEGF;
            bufF[0][2 * i] = acur0;
        }
        if (act1) {
            acur1 = (2 * i + 1 <= 1) ? lpL[u] : NEGF;
            bufF[0][2 * i + 1] = acur1;
            d_alphaU[blkBase * Uu + u] = acur1;
        }
        const int nChunks = (hlen + CH - 1) / CH;
        loadChunk(0, 0);
        CP_COMMIT();
        CP_WAIT(0);
        __syncthreads();
        int t = 1;
        for (int c = 0; c < nChunks; c++) {
            if (c + 1 < nChunks) { loadChunk((c + 1) & 1, (c + 1) * CH); CP_COMMIT(); }
            const int cb = c & 1;
            const int tEnd = min((c + 1) * CH, hlen);
            for (; t < tEnd; t++) {
                const int p = (t - 1) & 1;
                const int tt = t - c * CH;
                float emb = emB[cb][tt];
                float eml = act1 ? emL[cb][tt][u] : 0.f;
                float nb = (i >= 1) ? bufF[p][2 * i - 1] : NEGF;
                float nv0 = NEGF, nv1 = NEGF;
                if (act0) {
                    float mm = fmaxf(acur0, nb);
                    if (mm > THRF)
                        nv0 = emb + mm + __logf(__expf(acur0 - mm) + __expf(nb - mm));
                }
                if (act1) {
                    float x2 = allowOdd[u] ? nb : NEGF;
                    float mm = fmaxf(acur1, fmaxf(acur0, x2));
                    if (mm > THRF)
                        nv1 = eml + mm + __logf(__expf(acur1 - mm) + __expf(acur0 - mm)
                                                + __expf(x2 - mm));
                    d_alphaU[(blkBase + t) * Uu + u] = nv1;
                }
                if (act0) {
                    bufF[p ^ 1][2 * i] = nv0;
                    bufF[p ^ 1][2 * i + 1] = nv1;
                }
                acur0 = nv0; acur1 = nv1;
                __syncthreads();
            }
            if (c + 1 < nChunks) CP_WAIT(0);
            __syncthreads();
        }
    } else {
        const double fin0 = (i == olen) ? 0.0 : NEG_D;
        const double fin1 = (i == olen - 1) ? 0.0 : NEG_D;
        double carry0 = NEG_D, carry1 = NEG_D;
        const int cTop = (hlen - 1) / CH;
        loadChunk(cTop & 1, cTop * CH + 1);
        CP_COMMIT();
        CP_WAIT(0);
        __syncthreads();
        int t = hlen - 1;
        for (int c = cTop; c >= 0; c--) {
            if (c > 0) { loadChunk((c - 1) & 1, (c - 1) * CH + 1); CP_COMMIT(); }
            const int cb = c & 1;
            const int tLo = c * CH;
            for (; t >= tLo; t--) {
                const int pb = t & 1;
                const int tt = t - c * CH;
                float emb = emB[cb][tt];
                float eml = act1 ? emL[cb][tt][u] : 0.f;
                double g0  = act0 ? ((double)emb + carry0) : NEG_D;
                double g1v = act1 ? ((double)eml + carry1) : NEG_D;
                if (act0) {
                    bufD[pb][2 * i] = g0;
                    bufD[pb][2 * i + 1] = g1v;
                }
                __syncthreads();
                double nv0 = NEG_D, nv1 = NEG_D;
                if (act0) nv0 = lse2_64(g0, g1v);
                if (act1) {
                    double gn2 = bufD[pb][2 * i + 2];
                    double gn3 = allowOdd[i + 1] ? bufD[pb][2 * i + 3] : NEG_D;
                    nv1 = lse3_64(g1v, gn2, gn3);
                }
                if (t == hlen - 1) { nv0 = fin0; nv1 = fin1; }
                carry0 = nv0; carry1 = nv1;
                if (act1) d_betaU[(blkBase + t) * Uu + u] = nv1;
            }
            if (c > 0) CP_WAIT(0);
            __syncthreads();
        }
    }
}

// ============================================================================
// _log_sub_exp — reference branch semantics, no double transcendentals.
// ============================================================================
__device__ __forceinline__ double lse_ref_fast(double a, double b)
{
    if (a <= THR_D) return NEG_D;
    if (b <= THR_D) return a;
    double d = a - b;
    if (d == 0.0) return SENT_D;
    if (d <  0.0) return NEG_D;
    if (d >= 709.782712893384) return SENT_D;
    if (d > 80.0) return a;
    float df = (float)d;
    float v = (df < 6e-8f) ? logf(df) : logf(expm1f(df));
    return b + (double)v;
}

// ============================================================================
// K4a: per (b, chunk) partial online LSE — unchanged from R15.
// IDEMPOTENT: an instance at launch index 3 gets profiled (reads previous
// replay's alpha/beta in steady state = real data); its outputs are
// overwritten by the post-k_ab instance, so correctness is unaffected.
// ============================================================================
__global__ __launch_bounds__(256) void k_chunk()
{
    const int b = blockIdx.x;
    const int c = blockIdx.y;
    const int tid = threadIdx.x;
    __shared__ int s_olen;
    if (tid == 0) {
        int cc = 0;
        for (int q = 0; q < Uu; q++) cc += (d_ys[b * Uu + q] >= 0);
        s_olen = cc;
    }
    __syncthreads();
    if (tid >= Uu) return;
    const int u = tid;
    const int olen = s_olen;
    const int hlen = d_hl[b];
    const bool uv = u < olen;
    const size_t base = ((size_t)b * Tt) * Uu + u;
    const double invh = 1.0 / (double)hlen;
    const int t0 = c * TCH;

    auto vA = [&](int t) { return uv && t < hlen; };
    auto ldA = [&](int t) { int k = t > Tt - 1 ? Tt - 1 : t;
                            return vA(t) ? (double)d_alphaU[base + (size_t)k * Uu] : NEG_D; };
    auto ldB = [&](int t) { int k = t > Tt - 1 ? Tt - 1 : t;
                            return vA(t) ? d_betaU[base + (size_t)k * Uu] : NEG_D; };
    auto ldP = [&](int t) { int k = t > Tt - 1 ? Tt - 1 : t;
                            return vA(t) ? (double)d_lpLabel[base + (size_t)k * Uu] : NEG_D; };

    double a_c = ldA(t0);
    double b_c = ldB(t0);
    double b_n = ldB(t0 + 1);
    double p_n = ldP(t0 + 1);

    double m = NEG_D, ssum = 0.0;
#pragma unroll 2
    for (int tt = 0; tt < TCH; tt++) {
        const int t = t0 + tt;
        double a_n  = ldA(t + 1);
        double b_n2 = ldB(t + 2);
        double p_n2 = ldP(t + 2);

        double bp;
        if (t < Tt - 1) {
            double bsum = p_n + b_n;
            bp = lse_ref_fast(b_c, bsum);
        } else {
            bp = b_c;
        }
        double risk = 0.1 * ((double)(t + 1) * invh);
        double ls = (a_c + bp) + risk;
        if (ls > THR_D) {
            if (ls > m) {
                ssum = ssum * (double)__expf((float)(m - ls)) + 1.0;
                m = ls;
            } else {
                ssum += (double)__expf((float)(ls - m));
            }
        }
        a_c = a_n; b_c = b_n; b_n = b_n2; p_n = p_n2;
    }
    d_partM[((size_t)b * Uu + u) * NCH + c] = m;
    d_partS[((size_t)b * Uu + u) * NCH + c] = ssum;
}

// ============================================================================
// K4b: merge chunks per u, pick last finite u, write per-batch loss.
// ============================================================================
__global__ __launch_bounds__(256) void k_lossu()
{
    const int b = blockIdx.x;
    const int tid = threadIdx.x;
    __shared__ int s_olen;
    __shared__ double s_lu[256];
    if (tid == 0) {
        int cc = 0;
        for (int q = 0; q < Uu; q++) cc += (d_ys[b * Uu + q] >= 0);
        s_olen = cc;
    }
    __syncthreads();
    const int olen = s_olen;
    const int hlen = d_hl[b];

    double lu = NEG_D;
    if (tid < Uu) {
        const size_t pb = ((size_t)b * Uu + tid) * NCH;
        double M = NEG_D;
        for (int c = 0; c < NCH; c++) {
            double mc = d_partM[pb + c];
            if (mc > M) M = mc;
        }
        if (M > THR_D) {
            double S = 0.0;
            for (int c = 0; c < NCH; c++) {
                double mc = d_partM[pb + c];
                double sc = d_partS[pb + c];
                if (sc > 0.0) S += sc * (double)__expf((float)(mc - M));
            }
            if (S > 0.0) lu = M + (double)logf((float)S);
        }
    }
    s_lu[tid] = lu;
    __syncthreads();
    if (tid == 0) {
        int cnt = 0;
        for (int q = 0; q < Uu; q++) cnt += (s_lu[q] > THR_D);
        int last = cnt > 0 ? cnt - 1 : 0;
        double lf = s_lu[last];
        if (hlen < olen) lf = 0.0;
        d_lossB[b] = lf;
    }
}

// ============================================================================
// K5: final mean
// ============================================================================
__global__ void k_final(void* __restrict__ out)
{
    double s = 0.0;
    for (int i = 0; i < Bb; i++) s += d_lossB[i];
    double v = -s / (double)Bb;
    if (d_mode64) ((double*)out)[0] = v;
    else          ((float*)out)[0]  = (float)v;
}

// ============================================================================
extern "C" void kernel_launch(void* const* d_in, const int* in_sizes, int n_in,
                              void* d_out, int out_size)
{
    (void)out_size;
    const float* hs    = (const float*)d_in[0];
    const float* Wm    = (const float*)d_in[1];
    const float* bias  = (const float*)d_in[2];
    const void*  hlens = d_in[3];
    const void*  ys    = d_in[4];
    int ysSeen = 0;
    for (int i = 0; i < n_in; i++) {
        switch (in_sizes[i]) {
            case NA:      hs = (const float*)d_in[i]; break;
            case NW:      Wm = (const float*)d_in[i]; break;
            case Oo:      bias = (const float*)d_in[i]; break;
            case Bb:      hlens = d_in[i]; break;
            case Bb * Uu:
                if (ysSeen == 0) ys = d_in[i];
                ysSeen++;
                break;
            default: break;
        }
    }

    dim3 g1(Oo / 128, (Bb * Tt) / 128);
    dim3 gc(Bb, NCH);
    k_prep  <<<NB_CVT + 1, 256>>>(hs, Wm, ys, hlens);  // 0
    k_gemm  <<<g1, 512>>>(bias);                        // 1
    k_rowlse<<<Bb * Tt, 256>>>();                       // 2
    k_chunk <<<gc, 256>>>();                            // 3 <- profiled slot (dummy; real data in steady-state replays)
    k_ab    <<<2 * Bb, 224>>>();                        // 4
    k_ab    <<<2 * Bb, 224>>>();                        // 5 (idempotent duplicate: measures X_ab)
    k_chunk <<<gc, 256>>>();                            // 6 (authoritative; also duplicate: measures X_chunk)
    k_lossu <<<Bb, 256>>>();                            // 7
    k_final <<<1, 1>>>(d_out);                          // 8
}

// round 17
// speedup vs baseline: 4.3780x; 4.3780x over previous
#include <cuda_runtime.h>
#include <cuda_bf16.h>
#include <math.h>
#include <stdint.h>

#define Bb 16
#define Tt 1600
#define Ee 512
#define Oo 2048
#define Uu 200
#define Ss 401
#define NCH 32
#define TCH (Tt / NCH)
#define CH 24

#define NEGF  (-1.0e30f)
#define THRF  (-1.0e29f)
#define NEG_D (-1.0e30)
#define THR_D (-1.0e29)
#define SENT_D (-2000.4586751453871)

#define NA (Bb * Tt * Ee)
#define NW (Oo * Ee)
#define NB_CVT ((NA + NW) / 1024)

// ------------------------- static scratch -------------------------
static __device__ float          d_logits[(size_t)Bb * Tt * Oo];
static __device__ __nv_bfloat16  d_hsb[(size_t)NA];
static __device__ __nv_bfloat16  d_Wb[(size_t)NW];
static __device__ float  d_lpBlank[Bb * Tt];
static __device__ float  d_lpLabel[(size_t)Bb * Tt * Uu];
static __device__ float  d_alphaU[(size_t)Bb * Tt * Uu];
static __device__ double d_betaU[(size_t)Bb * Tt * Uu];
static __device__ double d_partM[(size_t)Bb * Uu * NCH];
static __device__ double d_partS[(size_t)Bb * Uu * NCH];
static __device__ double d_lossB[Bb];
static __device__ int    d_ys[Bb * Uu];
static __device__ int    d_hl[Bb];
static __device__ int    d_mode64;

// ============================================================================
// K0: fused repack + bf16 convert
// ============================================================================
__global__ __launch_bounds__(256) void k_prep(const float* __restrict__ hs,
                                              const float* __restrict__ Wm,
                                              const void* ysRaw, const void* hlRaw)
{
    const int tid = threadIdx.x;
    if (blockIdx.x == NB_CVT) {
        const int* y32 = (const int*)ysRaw;
        int anyPos = __syncthreads_or(y32[2 * tid + 1] > 0);
        const int m64 = (anyPos == 0);
        if (tid == 0) d_mode64 = m64;
        for (int i = tid; i < Bb * Uu; i += 256)
            d_ys[i] = m64 ? (int)((const long long*)ysRaw)[i] : ((const int*)ysRaw)[i];
        if (tid < Bb)
            d_hl[tid] = m64 ? (int)((const long long*)hlRaw)[tid] : ((const int*)hlRaw)[tid];
        return;
    }
    const size_t i = ((size_t)blockIdx.x * 256 + tid) * 4;
    if (i < (size_t)NA) {
        float4 v = *(const float4*)(hs + i);
        ushort4 o;
        o.x = __bfloat16_as_ushort(__float2bfloat16_rn(v.x));
        o.y = __bfloat16_as_ushort(__float2bfloat16_rn(v.y));
        o.z = __bfloat16_as_ushort(__float2bfloat16_rn(v.z));
        o.w = __bfloat16_as_ushort(__float2bfloat16_rn(v.w));
        *(ushort4*)(d_hsb + i) = o;
    } else {
        const size_t j = i - NA;
        float4 v = *(const float4*)(Wm + j);
        ushort4 o;
        o.x = __bfloat16_as_ushort(__float2bfloat16_rn(v.x));
        o.y = __bfloat16_as_ushort(__float2bfloat16_rn(v.y));
        o.z = __bfloat16_as_ushort(__float2bfloat16_rn(v.z));
        o.w = __bfloat16_as_ushort(__float2bfloat16_rn(v.w));
        *(ushort4*)(d_Wb + j) = o;
    }
}

// ============================================================================
// cp.async helpers
// ============================================================================
__device__ __forceinline__ void cp16(void* smem, const void* gmem)
{
    uint32_t s = (uint32_t)__cvta_generic_to_shared(smem);
    asm volatile("cp.async.cg.shared.global [%0], [%1], 16;\n" :: "r"(s), "l"(gmem));
}
__device__ __forceinline__ void cp4(void* smem, const void* gmem)
{
    uint32_t s = (uint32_t)__cvta_generic_to_shared(smem);
    asm volatile("cp.async.ca.shared.global [%0], [%1], 4;\n" :: "r"(s), "l"(gmem));
}
#define CP_COMMIT() asm volatile("cp.async.commit_group;\n" ::: "memory")
#define CP_WAIT(n)  asm volatile("cp.async.wait_group %0;\n" :: "n"(n) : "memory")

// ============================================================================
// K1: bf16 mma GEMM (measured 222 us) — unchanged
// ============================================================================
__global__ __launch_bounds__(512) void k_gemm(const float* __restrict__ bias)
{
    __shared__ __align__(16) __nv_bfloat16 As[2][128][40];
    __shared__ __align__(16) __nv_bfloat16 Ws[2][128][40];

    const int tid  = threadIdx.x;
    const int bn   = blockIdx.x, bm = blockIdx.y;
    const int lane = tid & 31;
    const int warp = tid >> 5;
    const int g    = lane >> 2;
    const int t    = lane & 3;
    const int wm   = warp >> 2;
    const int wn   = warp & 3;

    const int r = tid >> 2;
    const int q = (tid & 3) << 3;
    const __nv_bfloat16* Ap = d_hsb + ((size_t)(bm * 128 + r)) * Ee + q;
    const __nv_bfloat16* Wp = d_Wb  + ((size_t)(bn * 128 + r)) * Ee + q;

    float acc[2][4][4];
#pragma unroll
    for (int mi = 0; mi < 2; mi++)
#pragma unroll
        for (int ni = 0; ni < 4; ni++)
#pragma unroll
            for (int c = 0; c < 4; c++) acc[mi][ni][c] = 0.f;

    cp16(&As[0][r][q], Ap);
    cp16(&Ws[0][r][q], Wp);
    CP_COMMIT();

    const int rA0 = wm * 32 + g;
    const int nB0 = wn * 32 + g;

#pragma unroll 1
    for (int kt = 0; kt < 16; kt++) {
        const int buf = kt & 1;
        if (kt < 15) {
            cp16(&As[buf ^ 1][r][q], Ap + (kt + 1) * 32);
            cp16(&Ws[buf ^ 1][r][q], Wp + (kt + 1) * 32);
            CP_COMMIT();
            CP_WAIT(1);
        } else {
            CP_WAIT(0);
        }
        __syncthreads();
#pragma unroll
        for (int ks = 0; ks < 2; ks++) {
            const int kk = ks * 16;
            uint32_t af[2][4], bf[4][2];
#pragma unroll
            for (int mi = 0; mi < 2; mi++) {
                const int rr = rA0 + mi * 16;
                af[mi][0] = *(const uint32_t*)&As[buf][rr][kk + 2 * t];
                af[mi][1] = *(const uint32_t*)&As[buf][rr + 8][kk + 2 * t];
                af[mi][2] = *(const uint32_t*)&As[buf][rr][kk + 2 * t + 8];
                af[mi][3] = *(const uint32_t*)&As[buf][rr + 8][kk + 2 * t + 8];
            }
#pragma unroll
            for (int ni = 0; ni < 4; ni++) {
                const int nn = nB0 + ni * 8;
                bf[ni][0] = *(const uint32_t*)&Ws[buf][nn][kk + 2 * t];
                bf[ni][1] = *(const uint32_t*)&Ws[buf][nn][kk + 2 * t + 8];
            }
#pragma unroll
            for (int mi = 0; mi < 2; mi++)
#pragma unroll
                for (int ni = 0; ni < 4; ni++) {
                    asm volatile(
                        "mma.sync.aligned.m16n8k16.row.col.f32.bf16.bf16.f32 "
                        "{%0,%1,%2,%3}, {%4,%5,%6,%7}, {%8,%9}, {%0,%1,%2,%3};"
                        : "+f"(acc[mi][ni][0]), "+f"(acc[mi][ni][1]),
                          "+f"(acc[mi][ni][2]), "+f"(acc[mi][ni][3])
                        : "r"(af[mi][0]), "r"(af[mi][1]),
                          "r"(af[mi][2]), "r"(af[mi][3]),
                          "r"(bf[ni][0]), "r"(bf[ni][1]));
                }
        }
        __syncthreads();
    }

#pragma unroll
    for (int mi = 0; mi < 2; mi++) {
        const int row0 = bm * 128 + wm * 32 + mi * 16 + g;
#pragma unroll
        for (int ni = 0; ni < 4; ni++) {
            const int col = bn * 128 + wn * 32 + ni * 8 + 2 * t;
            const float2 bb = *(const float2*)&bias[col];
            float2 v0 = make_float2(acc[mi][ni][0] + bb.x, acc[mi][ni][1] + bb.y);
            float2 v1 = make_float2(acc[mi][ni][2] + bb.x, acc[mi][ni][3] + bb.y);
            *(float2*)(d_logits + (size_t)row0 * Oo + col) = v0;
            *(float2*)(d_logits + (size_t)(row0 + 8) * Oo + col) = v1;
        }
    }
}

// ============================================================================
// K2: row LSE + gather — unchanged (measured 50 us)
// ============================================================================
__global__ __launch_bounds__(256) void k_rowlse()
{
    const int row = blockIdx.x;
    const int b = row / Tt;
    const int tid = threadIdx.x;
    __shared__ float sr[Oo];
    __shared__ float red[32];
    const float4* r4 = (const float4*)(d_logits + (size_t)row * Oo);

    float4 va = r4[tid];
    float4 vb = r4[tid + 256];
    ((float4*)sr)[tid] = va;
    ((float4*)sr)[tid + 256] = vb;
    float m = fmaxf(fmaxf(fmaxf(va.x, va.y), fmaxf(va.z, va.w)),
                    fmaxf(fmaxf(vb.x, vb.y), fmaxf(vb.z, vb.w)));
    for (int o = 16; o; o >>= 1) m = fmaxf(m, __shfl_xor_sync(0xffffffffu, m, o));
    if ((tid & 31) == 0) red[tid >> 5] = m;
    __syncthreads();
    if (tid < 32) {
        float x = (tid < 8) ? red[tid] : -3.0e38f;
        for (int o = 4; o; o >>= 1) x = fmaxf(x, __shfl_xor_sync(0xffffffffu, x, o));
        if (tid == 0) red[0] = x;
    }
    __syncthreads();
    m = red[0];

    float s = __expf(va.x - m) + __expf(va.y - m) + __expf(va.z - m) + __expf(va.w - m)
            + __expf(vb.x - m) + __expf(vb.y - m) + __expf(vb.z - m) + __expf(vb.w - m);
    for (int o = 16; o; o >>= 1) s += __shfl_xor_sync(0xffffffffu, s, o);
    __syncthreads();
    if ((tid & 31) == 0) red[tid >> 5] = s;
    __syncthreads();
    if (tid < 32) {
        float x = (tid < 8) ? red[tid] : 0.f;
        for (int o = 4; o; o >>= 1) x += __shfl_xor_sync(0xffffffffu, x, o);
        if (tid == 0) red[1] = x;
    }
    __syncthreads();
    const float lse = m + logf(red[1]);

    if (tid == 0) d_lpBlank[row] = sr[0] - lse;
    if (tid < Uu) {
        int y = d_ys[b * Uu + tid];
        int c = y < 0 ? 0 : y;
        d_lpLabel[(size_t)row * Uu + tid] = sr[c] - lse;
    }
}

// fast y = log1p(x) for x >= 0: exact-enough relative accuracy at all scales.
__device__ __forceinline__ float log1pf_fast(float x)
{
    return (x < 1e-4f) ? x : __logf(1.0f + x);
}

// ============================================================================
// K3: alpha (blocks 0..15, f32) / beta (blocks 16..31, FP64-minimal).
// Beta keeps ONLY the bit-critical f64 ops: g = em + carry (DADD),
// nv = m + y (DADD), and exact-f64 m (selected). All diffs/exps/log in f32
// off an f32 shadow buffer. Relative accuracy of y preserves the
// m+y==m degeneracy band to ~1e-7 measure.
// ============================================================================
__global__ __launch_bounds__(224) void k_ab()
{
    const int b = blockIdx.x & (Bb - 1);
    const bool isBeta = (blockIdx.x >= Bb);
    const int i = threadIdx.x;
    __shared__ __align__(16) double bufD[2][408];
    __shared__ __align__(8)  float  bufF[2][408];
    __shared__ bool allowOdd[208];
    __shared__ int s_olen;
    __shared__ __align__(16) float emL[2][CH][Uu];
    __shared__ float emB[2][CH];

    for (int k = i; k < 408; k += 224) {
        bufD[0][k] = NEG_D; bufD[1][k] = NEG_D;
        bufF[0][k] = NEGF;  bufF[1][k] = NEGF;
    }
    if (i < 208) allowOdd[i] = false;
    __syncthreads();
    if (i >= 1 && i < Uu) {
        int yu = d_ys[b * Uu + i];
        int yp = d_ys[b * Uu + i - 1];
        int cu = yu < 0 ? 0 : yu;
        int cp = yp < 0 ? 0 : yp;
        allowOdd[i] = (cu != cp);
    }
    if (i == 0) {
        int c = 0;
        for (int q = 0; q < Uu; q++) c += (d_ys[b * Uu + q] >= 0);
        s_olen = c;
    }
    __syncthreads();
    const int hlen = d_hl[b];
    const int olen = s_olen;
    const bool act0 = (i <= 200);
    const bool act1 = (i <= 199);
    const int u = i;
    const size_t blkBase = (size_t)b * Tt;
    const float* lpL = d_lpLabel + blkBase * Uu;
    const float* lpB = d_lpBlank + blkBase;

    auto loadChunk = [&](int nb, int r0) {
        for (int k = i; k < CH * (Uu / 4); k += 224) {
            int tt = k / (Uu / 4);
            int j  = k % (Uu / 4);
            int row = r0 + tt;
            if (row > Tt - 1) row = Tt - 1;
            if (row < 0) row = 0;
            cp16(&emL[nb][tt][j * 4], lpL + (size_t)row * Uu + j * 4);
        }
        if (i < CH) {
            int row = r0 + i;
            if (row > Tt - 1) row = Tt - 1;
            if (row < 0) row = 0;
            cp4(&emB[nb][i], lpB + row);
        }
    };

    if (!isBeta) {
        // ---------------- alpha forward (f32) — same math as R15 ----------------
        float acur0 = NEGF, acur1 = NEGF;
        if (act0) {
            acur0 = (2 * i <= 1) ? lpB[0] : NEGF;
            bufF[0][2 * i] = acur0;
        }
        if (act1) {
            acur1 = (2 * i + 1 <= 1) ? lpL[u] : NEGF;
            bufF[0][2 * i + 1] = acur1;
            d_alphaU[blkBase * Uu + u] = acur1;
        }
        const int nChunks = (hlen + CH - 1) / CH;
        loadChunk(0, 0);
        CP_COMMIT();
        CP_WAIT(0);
        __syncthreads();
        int t = 1;
        for (int c = 0; c < nChunks; c++) {
            if (c + 1 < nChunks) { loadChunk((c + 1) & 1, (c + 1) * CH); CP_COMMIT(); }
            const int cb = c & 1;
            const int tEnd = min((c + 1) * CH, hlen);
            for (; t < tEnd; t++) {
                const int p = (t - 1) & 1;
                const int tt = t - c * CH;
                float emb = emB[cb][tt];
                float eml = act1 ? emL[cb][tt][u] : 0.f;
                float nb = (i >= 1) ? bufF[p][2 * i - 1] : NEGF;
                float nv0 = NEGF, nv1 = NEGF;
                if (act0) {
                    float mm = fmaxf(acur0, nb);
                    if (mm > THRF)
                        nv0 = emb + mm + __logf(__expf(acur0 - mm) + __expf(nb - mm));
                }
                if (act1) {
                    float x2 = allowOdd[u] ? nb : NEGF;
                    float mm = fmaxf(acur1, fmaxf(acur0, x2));
                    if (mm > THRF)
                        nv1 = eml + mm + __logf(__expf(acur1 - mm) + __expf(acur0 - mm)
                                                + __expf(x2 - mm));
                    d_alphaU[(blkBase + t) * Uu + u] = nv1;
                }
                if (act0) {
                    bufF[p ^ 1][2 * i] = nv0;
                    bufF[p ^ 1][2 * i + 1] = nv1;
                }
                acur0 = nv0; acur1 = nv1;
                __syncthreads();
            }
            if (c + 1 < nChunks) CP_WAIT(0);
            __syncthreads();
        }
    } else {
        // ---------------- beta backward (FP64-minimal) ----------------
        const double fin0 = (i == olen) ? 0.0 : NEG_D;
        const double fin1 = (i == olen - 1) ? 0.0 : NEG_D;
        double carry0 = NEG_D, carry1 = NEG_D;
        const int cTop = (hlen - 1) / CH;
        loadChunk(cTop & 1, cTop * CH + 1);
        CP_COMMIT();
        CP_WAIT(0);
        __syncthreads();
        int t = hlen - 1;
        for (int c = cTop; c >= 0; c--) {
            if (c > 0) { loadChunk((c - 1) & 1, (c - 1) * CH + 1); CP_COMMIT(); }
            const int cb = c & 1;
            const int tLo = c * CH;
            for (; t >= tLo; t--) {
                const int pb = t & 1;
                const int tt = t - c * CH;
                float emb = emB[cb][tt];
                float eml = act1 ? emL[cb][tt][u] : 0.f;
                double g0  = act0 ? ((double)emb + carry0) : NEG_D;   // exact DADD
                double g1v = act1 ? ((double)eml + carry1) : NEG_D;   // exact DADD
                float gf0 = (float)g0;
                float gf1 = (float)g1v;
                if (act0) {
                    *(double2*)&bufD[pb][2 * i] = make_double2(g0, g1v);
                    *(float2*)&bufF[pb][2 * i]  = make_float2(gf0, gf1);
                }
                __syncthreads();
                double nv0 = NEG_D, nv1 = NEG_D;
                if (act0) {
                    // even state: lse(g0, g1v) — both in registers
                    float fm = fmaxf(gf0, gf1);
                    if (fm > THRF) {
                        bool a0 = (gf0 >= gf1);
                        double m = a0 ? g0 : g1v;
                        float mf = a0 ? gf0 : gf1;
                        float xo = a0 ? gf1 : gf0;
                        float x = __expf(xo - mf);        // non-anchor only
                        nv0 = m + (double)log1pf_fast(x); // exact DADD
                    }
                }
                if (act1) {
                    // odd state: lse(g1v, gn2, gn3)
                    double2 gn = *(const double2*)&bufD[pb][2 * i + 2];
                    float2 gnf = *(const float2*)&bufF[pb][2 * i + 2];
                    bool al = allowOdd[i + 1];
                    double G3 = al ? gn.y : NEG_D;
                    float  F3 = al ? gnf.y : NEGF;
                    float fm = fmaxf(gf1, fmaxf(gnf.x, F3));
                    if (fm > THRF) {
                        double m; float mf, xa, xb;
                        if (gf1 >= gnf.x && gf1 >= F3) { m = g1v;  mf = gf1;   xa = gnf.x; xb = F3; }
                        else if (gnf.x >= F3)          { m = gn.x; mf = gnf.x; xa = gf1;   xb = F3; }
                        else                           { m = G3;   mf = F3;    xa = gf1;   xb = gnf.x; }
                        float x = __expf(xa - mf) + __expf(xb - mf);  // non-anchor sum
                        nv1 = m + (double)log1pf_fast(x);             // exact DADD
                    }
                }
                if (t == hlen - 1) { nv0 = fin0; nv1 = fin1; }
                carry0 = nv0; carry1 = nv1;
                if (act1) d_betaU[(blkBase + t) * Uu + u] = nv1;
            }
            if (c > 0) CP_WAIT(0);
            __syncthreads();
        }
    }
}

// ============================================================================
// _log_sub_exp — reference branch semantics, no double transcendentals.
// ============================================================================
__device__ __forceinline__ double lse_ref_fast(double a, double b)
{
    if (a <= THR_D) return NEG_D;
    if (b <= THR_D) return a;
    double d = a - b;
    if (d == 0.0) return SENT_D;
    if (d <  0.0) return NEG_D;
    if (d >= 709.782712893384) return SENT_D;
    if (d > 80.0) return a;
    float df = (float)d;
    float v = (df < 6e-8f) ? logf(df) : logf(expm1f(df));
    return b + (double)v;
}

// ============================================================================
// K4a: per (b, chunk) partial online LSE — unchanged from R15 (357 us measured)
// ============================================================================
__global__ __launch_bounds__(256) void k_chunk()
{
    const int b = blockIdx.x;
    const int c = blockIdx.y;
    const int tid = threadIdx.x;
    __shared__ int s_olen;
    if (tid == 0) {
        int cc = 0;
        for (int q = 0; q < Uu; q++) cc += (d_ys[b * Uu + q] >= 0);
        s_olen = cc;
    }
    __syncthreads();
    if (tid >= Uu) return;
    const int u = tid;
    const int olen = s_olen;
    const int hlen = d_hl[b];
    const bool uv = u < olen;
    const size_t base = ((size_t)b * Tt) * Uu + u;
    const double invh = 1.0 / (double)hlen;
    const int t0 = c * TCH;

    auto vA = [&](int t) { return uv && t < hlen; };
    auto ldA = [&](int t) { int k = t > Tt - 1 ? Tt - 1 : t;
                            return vA(t) ? (double)d_alphaU[base + (size_t)k * Uu] : NEG_D; };
    auto ldB = [&](int t) { int k = t > Tt - 1 ? Tt - 1 : t;
                            return vA(t) ? d_betaU[base + (size_t)k * Uu] : NEG_D; };
    auto ldP = [&](int t) { int k = t > Tt - 1 ? Tt - 1 : t;
                            return vA(t) ? (double)d_lpLabel[base + (size_t)k * Uu] : NEG_D; };

    double a_c = ldA(t0);
    double b_c = ldB(t0);
    double b_n = ldB(t0 + 1);
    double p_n = ldP(t0 + 1);

    double m = NEG_D, ssum = 0.0;
#pragma unroll 2
    for (int tt = 0; tt < TCH; tt++) {
        const int t = t0 + tt;
        double a_n  = ldA(t + 1);
        double b_n2 = ldB(t + 2);
        double p_n2 = ldP(t + 2);

        double bp;
        if (t < Tt - 1) {
            double bsum = p_n + b_n;       // identical DADD order to recursion's g
            bp = lse_ref_fast(b_c, bsum);
        } else {
            bp = b_c;
        }
        double risk = 0.1 * ((double)(t + 1) * invh);
        double ls = (a_c + bp) + risk;
        if (ls > THR_D) {
            if (ls > m) {
                ssum = ssum * (double)__expf((float)(m - ls)) + 1.0;
                m = ls;
            } else {
                ssum += (double)__expf((float)(ls - m));
            }
        }
        a_c = a_n; b_c = b_n; b_n = b_n2; p_n = p_n2;
    }
    d_partM[((size_t)b * Uu + u) * NCH + c] = m;
    d_partS[((size_t)b * Uu + u) * NCH + c] = ssum;
}

// ============================================================================
// K4b: merge chunks per u, pick last finite u, write per-batch loss.
// ============================================================================
__global__ __launch_bounds__(256) void k_lossu()
{
    const int b = blockIdx.x;
    const int tid = threadIdx.x;
    __shared__ int s_olen;
    __shared__ double s_lu[256];
    if (tid == 0) {
        int cc = 0;
        for (int q = 0; q < Uu; q++) cc += (d_ys[b * Uu + q] >= 0);
        s_olen = cc;
    }
    __syncthreads();
    const int olen = s_olen;
    const int hlen = d_hl[b];

    double lu = NEG_D;
    if (tid < Uu) {
        const size_t pb = ((size_t)b * Uu + tid) * NCH;
        double M = NEG_D;
        for (int c = 0; c < NCH; c++) {
            double mc = d_partM[pb + c];
            if (mc > M) M = mc;
        }
        if (M > THR_D) {
            double S = 0.0;
            for (int c = 0; c < NCH; c++) {
                double mc = d_partM[pb + c];
                double sc = d_partS[pb + c];
                if (sc > 0.0) S += sc * (double)__expf((float)(mc - M));
            }
            if (S > 0.0) lu = M + (double)logf((float)S);
        }
    }
    s_lu[tid] = lu;
    __syncthreads();
    if (tid == 0) {
        int cnt = 0;
        for (int q = 0; q < Uu; q++) cnt += (s_lu[q] > THR_D);
        int last = cnt > 0 ? cnt - 1 : 0;
        double lf = s_lu[last];
        if (hlen < olen) lf = 0.0;
        d_lossB[b] = lf;
    }
}

// ============================================================================
// K5: final mean
// ============================================================================
__global__ void k_final(void* __restrict__ out)
{
    double s = 0.0;
    for (int i = 0; i < Bb; i++) s += d_lossB[i];
    double v = -s / (double)Bb;
    if (d_mode64) ((double*)out)[0] = v;
    else          ((float*)out)[0]  = (float)v;
}

// ============================================================================
extern "C" void kernel_launch(void* const* d_in, const int* in_sizes, int n_in,
                              void* d_out, int out_size)
{
    (void)out_size;
    const float* hs    = (const float*)d_in[0];
    const float* Wm    = (const float*)d_in[1];
    const float* bias  = (const float*)d_in[2];
    const void*  hlens = d_in[3];
    const void*  ys    = d_in[4];
    int ysSeen = 0;
    for (int i = 0; i < n_in; i++) {
        switch (in_sizes[i]) {
            case NA:      hs = (const float*)d_in[i]; break;
            case NW:      Wm = (const float*)d_in[i]; break;
            case Oo:      bias = (const float*)d_in[i]; break;
            case Bb:      hlens = d_in[i]; break;
            case Bb * Uu:
                if (ysSeen == 0) ys = d_in[i];
                ysSeen++;
                break;
            default: break;
        }
    }

    dim3 g1(Oo / 128, (Bb * Tt) / 128);
    dim3 gc(Bb, NCH);
    k_prep  <<<NB_CVT + 1, 256>>>(hs, Wm, ys, hlens);
    k_gemm  <<<g1, 512>>>(bias);
    k_rowlse<<<Bb * Tt, 256>>>();
    k_ab    <<<2 * Bb, 224>>>();
    k_chunk <<<gc, 256>>>();
    k_lossu <<<Bb, 256>>>();
    k_final <<<1, 1>>>(d_out);
}